// round 3
// baseline (speedup 1.0000x reference)
#include <cuda_runtime.h>
#include <math.h>

#define BN   8
#define TT   12
#define NN   200
#define CIN  2
#define HH   64
#define DD   32
#define HST  64
#define GW   66      // CIN + HH
#define GIN  198     // GW * 3
#define FRU  128
#define FCAND 64

// ---------------- scratch (device globals; no allocation allowed) -------------
__device__ float g_state_dy[BN*NN*DD];
__device__ float g_state   [BN*NN*HH];
__device__ float g_Pg[BN*NN*DD];
__device__ float g_Qg[BN*NN*DD];
__device__ float g_Pm[BN*NN*DD];
__device__ float g_Qm[BN*NN*DD];
__device__ float g_A [BN*NN*NN];
__device__ float g_X1[BN*NN*GW];
__device__ float g_ru[BN*NN*2*HH];

__device__ __forceinline__ float fsig(float v){
    return __fdividef(1.f, 1.f + __expf(-v));
}

// ---------------- init: state_dy0 = nf @ W_s2d + b ; state = 0 ---------------
__global__ void init_kernel(const float* __restrict__ nf,
                            const float* __restrict__ W,
                            const float* __restrict__ bias)
{
    int idx = blockIdx.x*blockDim.x + threadIdx.x;
    int total = gridDim.x*blockDim.x;
    if (idx < NN*DD){
        int n = idx / DD, d = idx % DD;
        float acc = bias[d];
        #pragma unroll 8
        for (int k = 0; k < HST; k++) acc += nf[n*HST + k] * W[k*DD + d];
        for (int b = 0; b < BN; b++) g_state_dy[(b*NN + n)*DD + d] = acc;
    }
    for (int i = idx; i < BN*NN*HH; i += total) g_state[i] = 0.f;
}

// ---------------- GRU-dy + P/Q projections (one warp per node) ---------------
__global__ void gru_dy_kernel(const float* __restrict__ x, int t,
                              const float* __restrict__ W_rz, const float* __restrict__ b_rz,
                              const float* __restrict__ W_h,  const float* __restrict__ b_h,
                              const float* __restrict__ Wc2,  const float* __restrict__ bc2,
                              const float* __restrict__ Wm2,  const float* __restrict__ bm2)
{
    __shared__ float sh[8][96];  // per node: sd[32], rs[32], s[32]
    int warp = threadIdx.x >> 5, lane = threadIdx.x & 31;
    int node = blockIdx.x * 8 + warp;       // 200 blocks * 8 warps = 1600 nodes
    int b = node / NN, n = node % NN;
    float* sd = sh[warp];
    float* rs = sd + 32;
    float* sv = sd + 64;

    float inp1 = x[((b*TT + t)*NN + n)*CIN + 0];
    int base = node*DD;
    sd[lane] = g_state_dy[base + lane];
    __syncwarp();

    // rz = sigmoid([inp1, sd] @ W_rz + b_rz);   r = rz[:32], z = rz[32:]
    float accr = b_rz[lane]      + inp1 * W_rz[lane];
    float accz = b_rz[lane + 32] + inp1 * W_rz[lane + 32];
    #pragma unroll
    for (int d = 0; d < 32; d++){
        float v = sd[d];
        accr += v * W_rz[(1 + d)*64 + lane];
        accz += v * W_rz[(1 + d)*64 + lane + 32];
    }
    float r = fsig(accr), z = fsig(accz);
    rs[lane] = r * sd[lane];
    __syncwarp();

    float acch = b_h[lane] + inp1 * W_h[lane];
    #pragma unroll
    for (int d = 0; d < 32; d++) acch += rs[d] * W_h[(1 + d)*32 + lane];
    float h  = tanhf(acch);
    float nd = z * sd[lane] + (1.f - z) * h;
    g_state_dy[base + lane] = nd;
    float s = fmaxf(nd, 0.f);
    sv[lane] = s;
    __syncwarp();

    // P/Q projections: y@Wc2 = s_i@Wc2[:32] + s_j@Wc2[32:]
    float pg = 0.f, qg = bc2[lane], pm = 0.f, qm = bm2[lane];
    #pragma unroll
    for (int d = 0; d < 32; d++){
        float v = sv[d];
        pg += v * Wc2[d*32 + lane];
        qg += v * Wc2[(32 + d)*32 + lane];
        pm += v * Wm2[d*32 + lane];
        qm += v * Wm2[(32 + d)*32 + lane];
    }
    g_Pg[base + lane] = pg;  g_Qg[base + lane] = qg;
    g_Pm[base + lane] = pm;  g_Qm[base + lane] = qm;
}

// ---------------- pair kernel: A = g * sigmoid(m); writes A and dy_graphs[t] --
__global__ void pair_kernel(const float* __restrict__ Wc1, const float* __restrict__ bc1,
                            const float* __restrict__ Wm1, const float* __restrict__ bm1,
                            float* __restrict__ out_dy, int t)
{
    __shared__ float Pgs[16][33], Pms[16][33], Qgs[16][33], Qms[16][33];
    __shared__ float w1g[32], w1m[32];
    int b  = blockIdx.z;
    int i0 = blockIdx.y * 16, j0 = blockIdx.x * 16;
    int tid = threadIdx.x;

    if (tid < 32){ w1g[tid] = Wc1[tid]; w1m[tid] = Wm1[tid]; }
    for (int e = tid; e < 512; e += 256){
        int il = e >> 5, d = e & 31;
        int i = i0 + il, j = j0 + il;
        if (i < NN){ int idx = (b*NN + i)*DD + d; Pgs[il][d] = g_Pg[idx]; Pms[il][d] = g_Pm[idx]; }
        if (j < NN){ int idx = (b*NN + j)*DD + d; Qgs[il][d] = g_Qg[idx]; Qms[il][d] = g_Qm[idx]; }
    }
    __syncthreads();

    int tj = tid & 15, ti = tid >> 4;
    int i = i0 + ti, j = j0 + tj;
    if (i < NN && j < NN){
        float ga = bc1[0], ma = bm1[0];
        #pragma unroll
        for (int d = 0; d < 32; d++){
            float hg = fmaxf(Pgs[ti][d] + Qgs[tj][d], 0.f);
            ga += hg * w1g[d];
            float hm = fmaxf(Pms[ti][d] + Qms[tj][d], 0.f);
            ma += hm * w1m[d];
        }
        float A = ga * fsig(ma);
        int idx = (b*NN + i)*NN + j;
        g_A[idx] = A;
        out_dy[(size_t)t*BN*NN*NN + idx] = A;
    }
}

// ---------------- hop: X1 = A @ X0,  X0 = [xt, state] (or [xt, rr*state]) -----
template<int CAND>
__global__ void hop_kernel(const float* __restrict__ x, int t)
{
    extern __shared__ float sm[];
    float* X0s = sm;               // 200*66
    float* As  = sm + NN*GW;       // 8*200
    int b  = blockIdx.y;
    int i0 = blockIdx.x * 8;
    int tid = threadIdx.x;         // 128

    for (int e = tid; e < NN*GW; e += 128){
        int j = e / GW, c = e % GW;
        float v;
        if (c < CIN) v = x[((b*TT + t)*NN + j)*CIN + c];
        else {
            int k = c - CIN;
            float st = g_state[(b*NN + j)*HH + k];
            if (CAND) st *= g_ru[(b*NN + j)*(2*HH) + k];
            v = st;
        }
        X0s[e] = v;
    }
    for (int e = tid; e < 8*NN; e += 128){
        int il = e / NN, j = e % NN;
        As[e] = g_A[(b*NN + i0 + il)*NN + j];
    }
    __syncthreads();

    if (tid < GW){
        int c = tid;
        float acc[8] = {0.f,0.f,0.f,0.f,0.f,0.f,0.f,0.f};
        #pragma unroll 2
        for (int j = 0; j < NN; j++){
            float v = X0s[j*GW + c];
            #pragma unroll
            for (int il = 0; il < 8; il++) acc[il] += As[il*NN + j] * v;
        }
        #pragma unroll
        for (int il = 0; il < 8; il++)
            g_X1[(b*NN + i0 + il)*GW + c] = acc[il];
    }
}

// ------- conv: X2 = A@X1 (X1 shared-resident) fused with [X0,X1,X2]@W + act ---
template<int FOUT, int CAND>
__global__ void conv_kernel(const float* __restrict__ x, int t,
                            const float* __restrict__ W, const float* __restrict__ bias)
{
    extern __shared__ float sm[];
    float* X1s = sm;                    // 200*66  = 13200
    float* As  = sm + NN*GW;            // 8*200   = 1600
    float* Zs  = sm + NN*GW + 8*NN;     // 8*198   = 1584
    int b  = blockIdx.y;
    int i0 = blockIdx.x * 8;
    int tid = threadIdx.x;              // 128

    for (int e = tid; e < NN*GW; e += 128) X1s[e] = g_X1[b*NN*GW + e];
    for (int e = tid; e < 8*NN; e += 128){
        int il = e / NN, j = e % NN;
        As[e] = g_A[(b*NN + i0 + il)*NN + j];
    }
    __syncthreads();

    if (tid < GW){
        int c = tid;
        float acc[8] = {0.f,0.f,0.f,0.f,0.f,0.f,0.f,0.f};
        #pragma unroll 2
        for (int j = 0; j < NN; j++){
            float v = X1s[j*GW + c];
            #pragma unroll
            for (int il = 0; il < 8; il++) acc[il] += As[il*NN + j] * v;
        }
        #pragma unroll
        for (int il = 0; il < 8; il++){
            int i = i0 + il;
            Zs[il*GIN + 2*GW + c] = acc[il];          // X2
            Zs[il*GIN +   GW + c] = X1s[i*GW + c];    // X1 row i
            float v;
            if (c < CIN) v = x[((b*TT + t)*NN + i)*CIN + c];
            else {
                int k = c - CIN;
                float st = g_state[(b*NN + i)*HH + k];
                if (CAND) st *= g_ru[(b*NN + i)*(2*HH) + k];
                v = st;
            }
            Zs[il*GIN + c] = v;                        // X0 row i
        }
    }
    __syncthreads();

    constexpr int NG   = 128 / FOUT;   // groups of threads over il
    constexpr int ILPG = 8 / NG;       // rows per group
    int f   = tid % FOUT;
    int il0 = (tid / FOUT) * ILPG;

    float acc[ILPG];
    float bf = bias[f];
    #pragma unroll
    for (int q = 0; q < ILPG; q++) acc[q] = bf;
    #pragma unroll 2
    for (int k = 0; k < GIN; k++){
        float w = W[k*FOUT + f];
        #pragma unroll
        for (int q = 0; q < ILPG; q++) acc[q] += Zs[(il0 + q)*GIN + k] * w;
    }
    #pragma unroll
    for (int q = 0; q < ILPG; q++){
        int i = i0 + il0 + q;
        if (!CAND){
            g_ru[(b*NN + i)*(2*HH) + f] = fsig(acc[q]);
        } else {
            float cv = tanhf(acc[q]);
            float u  = g_ru[(b*NN + i)*(2*HH) + HH + f];
            float so = g_state[(b*NN + i)*HH + f];
            g_state[(b*NN + i)*HH + f] = u*so + (1.f - u)*cv;
        }
    }
}

// ---------------- final prediction head --------------------------------------
__global__ void pred_kernel(const float* __restrict__ Wp1, const float* __restrict__ bp1,
                            const float* __restrict__ Wp2, const float* __restrict__ bp2,
                            float* __restrict__ out)
{
    int node = blockIdx.x;          // 1600
    int tid  = threadIdx.x;         // 64
    __shared__ float ss[64];
    __shared__ float red[64];
    ss[tid] = g_state[node*HH + tid];
    __syncthreads();
    float acc = bp1[tid];
    #pragma unroll 8
    for (int k = 0; k < HH; k++) acc += ss[k] * Wp1[k*HH + tid];
    float hv = acc > 0.f ? acc : 0.01f*acc;   // leaky_relu slope 0.01
    red[tid] = hv * Wp2[tid];
    __syncthreads();
    for (int s = 32; s > 0; s >>= 1){
        if (tid < s) red[tid] += red[tid + s];
        __syncthreads();
    }
    if (tid == 0) out[node] = red[0] + bp2[0];
}

// ---------------- launch ------------------------------------------------------
extern "C" void kernel_launch(void* const* d_in, const int* in_sizes, int n_in,
                              void* d_out, int out_size)
{
    (void)in_sizes; (void)n_in; (void)out_size;
    const float* x        = (const float*)d_in[0];
    const float* nf       = (const float*)d_in[1];
    const float* W_s2d    = (const float*)d_in[2];
    const float* b_s2d    = (const float*)d_in[3];
    const float* W_rz     = (const float*)d_in[4];
    const float* b_rz     = (const float*)d_in[5];
    const float* W_h      = (const float*)d_in[6];
    const float* b_h      = (const float*)d_in[7];
    const float* Wc2      = (const float*)d_in[8];
    const float* bc2      = (const float*)d_in[9];
    const float* Wc1      = (const float*)d_in[10];
    const float* bc1      = (const float*)d_in[11];
    const float* Wm2      = (const float*)d_in[12];
    const float* bm2      = (const float*)d_in[13];
    const float* Wm1      = (const float*)d_in[14];
    const float* bm1      = (const float*)d_in[15];
    const float* W_ru     = (const float*)d_in[16];
    const float* b_ru     = (const float*)d_in[17];
    const float* W_cand   = (const float*)d_in[18];
    const float* b_cand   = (const float*)d_in[19];
    const float* Wp1      = (const float*)d_in[20];
    const float* bp1      = (const float*)d_in[21];
    const float* Wp2      = (const float*)d_in[22];
    const float* bp2      = (const float*)d_in[23];

    float* out      = (float*)d_out;
    float* out_pred = out;                 // (B,N,1) = 1600 floats
    float* out_dy   = out + BN*NN;         // (T,B,N,N)

    const int HOP_SMEM  = (NN*GW + 8*NN) * 4;           // 59200
    const int CONV_SMEM = (NN*GW + 8*NN + 8*GIN) * 4;   // 65536

    cudaFuncSetAttribute(hop_kernel<0>,  cudaFuncAttributeMaxDynamicSharedMemorySize, HOP_SMEM);
    cudaFuncSetAttribute(hop_kernel<1>,  cudaFuncAttributeMaxDynamicSharedMemorySize, HOP_SMEM);
    cudaFuncSetAttribute(conv_kernel<FRU,0>,   cudaFuncAttributeMaxDynamicSharedMemorySize, CONV_SMEM);
    cudaFuncSetAttribute(conv_kernel<FCAND,1>, cudaFuncAttributeMaxDynamicSharedMemorySize, CONV_SMEM);

    init_kernel<<<64, 128>>>(nf, W_s2d, b_s2d);

    for (int t = 0; t < TT; t++){
        gru_dy_kernel<<<200, 256>>>(x, t, W_rz, b_rz, W_h, b_h, Wc2, bc2, Wm2, bm2);
        pair_kernel<<<dim3(13,13,8), 256>>>(Wc1, bc1, Wm1, bm1, out_dy, t);
        hop_kernel<0><<<dim3(25,8), 128, HOP_SMEM>>>(x, t);
        conv_kernel<FRU,0><<<dim3(25,8), 128, CONV_SMEM>>>(x, t, W_ru, b_ru);
        hop_kernel<1><<<dim3(25,8), 128, HOP_SMEM>>>(x, t);
        conv_kernel<FCAND,1><<<dim3(25,8), 128, CONV_SMEM>>>(x, t, W_cand, b_cand);
    }

    pred_kernel<<<1600, 64>>>(Wp1, bp1, Wp2, bp2, out_pred);
}

// round 4
// speedup vs baseline: 1.5305x; 1.5305x over previous
#include <cuda_runtime.h>
#include <math.h>

#define BN   8
#define TT   12
#define NN   200
#define CIN  2
#define HH   64
#define DD   32
#define HST  64
#define GW   66      // CIN + HH
#define GIN  198     // GW * 3
#define FRU  128
#define FCAND 64

// ---------------- scratch (device globals; no allocation allowed) -------------
__device__ float g_state_dy[BN*NN*DD];
__device__ float g_state   [BN*NN*HH];
__device__ float g_Pg[BN*NN*DD];
__device__ float g_Qg[BN*NN*DD];
__device__ float g_Pm[BN*NN*DD];
__device__ float g_Qm[BN*NN*DD];
__device__ float g_A [BN*NN*NN];
__device__ float g_X1[BN*NN*GW];
__device__ float g_ru[BN*NN*2*HH];
__device__ float g_X0r[BN*NN*GW];   // [xt, state]       (ru path)
__device__ float g_X0c[BN*NN*GW];   // [xt, rr*state]    (cand path)

__device__ __forceinline__ float fsig(float v){
    return __fdividef(1.f, 1.f + __expf(-v));
}

// ---------------- init: state_dy0 = nf @ W_s2d + b ; state = 0 ---------------
__global__ void init_kernel(const float* __restrict__ nf,
                            const float* __restrict__ W,
                            const float* __restrict__ bias)
{
    int idx = blockIdx.x*blockDim.x + threadIdx.x;
    int total = gridDim.x*blockDim.x;
    if (idx < NN*DD){
        int n = idx / DD, d = idx % DD;
        float acc = bias[d];
        #pragma unroll 8
        for (int k = 0; k < HST; k++) acc += nf[n*HST + k] * W[k*DD + d];
        for (int b = 0; b < BN; b++) g_state_dy[(b*NN + n)*DD + d] = acc;
    }
    for (int i = idx; i < BN*NN*HH; i += total) g_state[i] = 0.f;
    for (int i = idx; i < BN*NN*GW; i += total) g_X0r[i] = 0.f;
}

// ---------------- GRU-dy + P/Q projections (one warp per node) ---------------
__global__ void gru_dy_kernel(const float* __restrict__ x, int t,
                              const float* __restrict__ W_rz, const float* __restrict__ b_rz,
                              const float* __restrict__ W_h,  const float* __restrict__ b_h,
                              const float* __restrict__ Wc2,  const float* __restrict__ bc2,
                              const float* __restrict__ Wm2,  const float* __restrict__ bm2)
{
    __shared__ float sh[8][96];  // per node: sd[32], rs[32], s[32]
    int warp = threadIdx.x >> 5, lane = threadIdx.x & 31;
    int node = blockIdx.x * 8 + warp;       // 200 blocks * 8 warps = 1600 nodes
    int b = node / NN, n = node % NN;
    float* sd = sh[warp];
    float* rs = sd + 32;
    float* sv = sd + 64;

    // write x columns of both X0 buffers for this step
    if (lane < CIN){
        float xv = x[((b*TT + t)*NN + n)*CIN + lane];
        g_X0r[(b*NN + n)*GW + lane] = xv;
        g_X0c[(b*NN + n)*GW + lane] = xv;
    }

    float inp1 = x[((b*TT + t)*NN + n)*CIN + 0];
    int base = node*DD;
    sd[lane] = g_state_dy[base + lane];
    __syncwarp();

    float accr = b_rz[lane]      + inp1 * W_rz[lane];
    float accz = b_rz[lane + 32] + inp1 * W_rz[lane + 32];
    #pragma unroll
    for (int d = 0; d < 32; d++){
        float v = sd[d];
        accr += v * W_rz[(1 + d)*64 + lane];
        accz += v * W_rz[(1 + d)*64 + lane + 32];
    }
    float r = fsig(accr), z = fsig(accz);
    rs[lane] = r * sd[lane];
    __syncwarp();

    float acch = b_h[lane] + inp1 * W_h[lane];
    #pragma unroll
    for (int d = 0; d < 32; d++) acch += rs[d] * W_h[(1 + d)*32 + lane];
    float h  = tanhf(acch);
    float nd = z * sd[lane] + (1.f - z) * h;
    g_state_dy[base + lane] = nd;
    float s = fmaxf(nd, 0.f);
    sv[lane] = s;
    __syncwarp();

    float pg = 0.f, qg = bc2[lane], pm = 0.f, qm = bm2[lane];
    #pragma unroll
    for (int d = 0; d < 32; d++){
        float v = sv[d];
        pg += v * Wc2[d*32 + lane];
        qg += v * Wc2[(32 + d)*32 + lane];
        pm += v * Wm2[d*32 + lane];
        qm += v * Wm2[(32 + d)*32 + lane];
    }
    g_Pg[base + lane] = pg;  g_Qg[base + lane] = qg;
    g_Pm[base + lane] = pm;  g_Qm[base + lane] = qm;
}

// ---------------- pair kernel: A = g * sigmoid(m); writes A and dy_graphs[t] --
__global__ void pair_kernel(const float* __restrict__ Wc1, const float* __restrict__ bc1,
                            const float* __restrict__ Wm1, const float* __restrict__ bm1,
                            float* __restrict__ out_dy, int t)
{
    __shared__ float Pgs[16][33], Pms[16][33], Qgs[16][33], Qms[16][33];
    __shared__ float w1g[32], w1m[32];
    int b  = blockIdx.z;
    int i0 = blockIdx.y * 16, j0 = blockIdx.x * 16;
    int tid = threadIdx.x;

    if (tid < 32){ w1g[tid] = Wc1[tid]; w1m[tid] = Wm1[tid]; }
    for (int e = tid; e < 512; e += 256){
        int il = e >> 5, d = e & 31;
        int i = i0 + il, j = j0 + il;
        if (i < NN){ int idx = (b*NN + i)*DD + d; Pgs[il][d] = g_Pg[idx]; Pms[il][d] = g_Pm[idx]; }
        if (j < NN){ int idx = (b*NN + j)*DD + d; Qgs[il][d] = g_Qg[idx]; Qms[il][d] = g_Qm[idx]; }
    }
    __syncthreads();

    int tj = tid & 15, ti = tid >> 4;
    int i = i0 + ti, j = j0 + tj;
    if (i < NN && j < NN){
        float ga = bc1[0], ma = bm1[0];
        #pragma unroll
        for (int d = 0; d < 32; d++){
            float hg = fmaxf(Pgs[ti][d] + Qgs[tj][d], 0.f);
            ga += hg * w1g[d];
            float hm = fmaxf(Pms[ti][d] + Qms[tj][d], 0.f);
            ma += hm * w1m[d];
        }
        float A = ga * fsig(ma);
        int idx = (b*NN + i)*NN + j;
        g_A[idx] = A;
        out_dy[(size_t)t*BN*NN*NN + idx] = A;
    }
}

// ---------------- hop: X1 = A @ X0 (X0 from global via L1, split-K) ----------
template<int CAND>
__global__ void __launch_bounds__(256) hop_kernel()
{
    __shared__ float As[8*NN];          // 6.4 KB
    __shared__ float Cp[3][8][GW];      // 6.3 KB partials
    const float* __restrict__ X0 = CAND ? g_X0c : g_X0r;
    int b = blockIdx.y, i0 = blockIdx.x*8;
    int tid = threadIdx.x;

    const float* Ab = g_A + (b*NN + i0)*NN;
    for (int e = tid; e < 8*NN; e += 256) As[e] = Ab[e];
    __syncthreads();

    if (tid < 3*GW){
        int grp = tid / GW;
        int c   = tid - grp*GW;
        int j0  = grp*68;
        int j1  = (grp == 2) ? NN : j0 + 68;   // 68/68/64, even-aligned
        const float* X0b = X0 + b*NN*GW + c;
        float acc[8];
        #pragma unroll
        for (int il = 0; il < 8; il++) acc[il] = 0.f;
        for (int j = j0; j < j1; j += 2){
            float v0 = __ldg(&X0b[j*GW]);
            float v1 = __ldg(&X0b[(j+1)*GW]);
            #pragma unroll
            for (int il = 0; il < 8; il++){
                float2 a = *(const float2*)&As[il*NN + j];
                acc[il] = fmaf(a.x, v0, acc[il]);
                acc[il] = fmaf(a.y, v1, acc[il]);
            }
        }
        #pragma unroll
        for (int il = 0; il < 8; il++) Cp[grp][il][c] = acc[il];
    }
    __syncthreads();

    for (int e = tid; e < 8*GW; e += 256){
        int il = e / GW, c = e - il*GW;
        g_X1[(b*NN + i0 + il)*GW + c] = Cp[0][il][c] + Cp[1][il][c] + Cp[2][il][c];
    }
}

// ------- conv: X2 = A@X1 (split-K, X1 via L1) fused with [X0,X1,X2]@W + act ---
template<int FOUT, int CAND>
__global__ void __launch_bounds__(256) conv_kernel(const float* __restrict__ W,
                                                   const float* __restrict__ bias)
{
    __shared__ float As[8*NN];          // 6.4 KB
    __shared__ float Cp[3][8][GW];      // 6.3 KB
    __shared__ float Zs[8][200];        // 6.4 KB (198 used)
    int b = blockIdx.y, i0 = blockIdx.x*8;
    int tid = threadIdx.x;

    const float* Ab = g_A + (b*NN + i0)*NN;
    for (int e = tid; e < 8*NN; e += 256) As[e] = Ab[e];
    __syncthreads();

    // phase A: X2 rows = A @ X1 (split-K over 3 groups)
    if (tid < 3*GW){
        int grp = tid / GW;
        int c   = tid - grp*GW;
        int j0  = grp*68;
        int j1  = (grp == 2) ? NN : j0 + 68;
        const float* X1b = g_X1 + b*NN*GW + c;
        float acc[8];
        #pragma unroll
        for (int il = 0; il < 8; il++) acc[il] = 0.f;
        for (int j = j0; j < j1; j += 2){
            float v0 = __ldg(&X1b[j*GW]);
            float v1 = __ldg(&X1b[(j+1)*GW]);
            #pragma unroll
            for (int il = 0; il < 8; il++){
                float2 a = *(const float2*)&As[il*NN + j];
                acc[il] = fmaf(a.x, v0, acc[il]);
                acc[il] = fmaf(a.y, v1, acc[il]);
            }
        }
        #pragma unroll
        for (int il = 0; il < 8; il++) Cp[grp][il][c] = acc[il];
    }
    __syncthreads();

    // assemble Z = [X0row | X1row | X2row]
    const float* __restrict__ X0 = CAND ? g_X0c : g_X0r;
    for (int e = tid; e < 8*GW; e += 256){
        int il = e / GW, c = e - il*GW;
        int row = (b*NN + i0 + il)*GW + c;
        Zs[il][c]        = X0[row];
        Zs[il][GW + c]   = g_X1[row];
        Zs[il][2*GW + c] = Cp[0][il][c] + Cp[1][il][c] + Cp[2][il][c];
    }
    __syncthreads();

    // phase B: Z @ W + bias, activation + epilogue
    constexpr int NGR  = 256 / FOUT;   // 2 (FOUT=128) or 4 (FOUT=64)
    constexpr int ILPG = 8 / NGR;      // 4 or 2
    int f   = tid % FOUT;
    int il0 = (tid / FOUT) * ILPG;

    float acc[ILPG];
    float bf = bias[f];
    #pragma unroll
    for (int q = 0; q < ILPG; q++) acc[q] = bf;
    #pragma unroll 2
    for (int k = 0; k < GIN; k++){
        float w = __ldg(&W[k*FOUT + f]);
        #pragma unroll
        for (int q = 0; q < ILPG; q++) acc[q] = fmaf(Zs[il0 + q][k], w, acc[q]);
    }
    #pragma unroll
    for (int q = 0; q < ILPG; q++){
        int i = i0 + il0 + q;
        if (!CAND){
            float rv = fsig(acc[q]);
            g_ru[(b*NN + i)*(2*HH) + f] = rv;
            if (f < HH){  // rr * state -> cand-path X0
                g_X0c[(b*NN + i)*GW + CIN + f] = rv * g_state[(b*NN + i)*HH + f];
            }
        } else {
            float cv = tanhf(acc[q]);
            float u  = g_ru[(b*NN + i)*(2*HH) + HH + f];
            float so = g_state[(b*NN + i)*HH + f];
            float ns = u*so + (1.f - u)*cv;
            g_state[(b*NN + i)*HH + f] = ns;
            g_X0r[(b*NN + i)*GW + CIN + f] = ns;   // next step's ru-path X0
        }
    }
}

// ---------------- final prediction head --------------------------------------
__global__ void pred_kernel(const float* __restrict__ Wp1, const float* __restrict__ bp1,
                            const float* __restrict__ Wp2, const float* __restrict__ bp2,
                            float* __restrict__ out)
{
    int node = blockIdx.x;          // 1600
    int tid  = threadIdx.x;         // 64
    __shared__ float ss[64];
    __shared__ float red[64];
    ss[tid] = g_state[node*HH + tid];
    __syncthreads();
    float acc = bp1[tid];
    #pragma unroll 8
    for (int k = 0; k < HH; k++) acc += ss[k] * Wp1[k*HH + tid];
    float hv = acc > 0.f ? acc : 0.01f*acc;   // leaky_relu slope 0.01
    red[tid] = hv * Wp2[tid];
    __syncthreads();
    for (int s = 32; s > 0; s >>= 1){
        if (tid < s) red[tid] += red[tid + s];
        __syncthreads();
    }
    if (tid == 0) out[node] = red[0] + bp2[0];
}

// ---------------- launch ------------------------------------------------------
extern "C" void kernel_launch(void* const* d_in, const int* in_sizes, int n_in,
                              void* d_out, int out_size)
{
    (void)in_sizes; (void)n_in; (void)out_size;
    const float* x        = (const float*)d_in[0];
    const float* nf       = (const float*)d_in[1];
    const float* W_s2d    = (const float*)d_in[2];
    const float* b_s2d    = (const float*)d_in[3];
    const float* W_rz     = (const float*)d_in[4];
    const float* b_rz     = (const float*)d_in[5];
    const float* W_h      = (const float*)d_in[6];
    const float* b_h      = (const float*)d_in[7];
    const float* Wc2      = (const float*)d_in[8];
    const float* bc2      = (const float*)d_in[9];
    const float* Wc1      = (const float*)d_in[10];
    const float* bc1      = (const float*)d_in[11];
    const float* Wm2      = (const float*)d_in[12];
    const float* bm2      = (const float*)d_in[13];
    const float* Wm1      = (const float*)d_in[14];
    const float* bm1      = (const float*)d_in[15];
    const float* W_ru     = (const float*)d_in[16];
    const float* b_ru     = (const float*)d_in[17];
    const float* W_cand   = (const float*)d_in[18];
    const float* b_cand   = (const float*)d_in[19];
    const float* Wp1      = (const float*)d_in[20];
    const float* bp1      = (const float*)d_in[21];
    const float* Wp2      = (const float*)d_in[22];
    const float* bp2      = (const float*)d_in[23];

    float* out      = (float*)d_out;
    float* out_pred = out;                 // (B,N,1) = 1600 floats
    float* out_dy   = out + BN*NN;         // (T,B,N,N)

    init_kernel<<<64, 128>>>(nf, W_s2d, b_s2d);

    for (int t = 0; t < TT; t++){
        gru_dy_kernel<<<200, 256>>>(x, t, W_rz, b_rz, W_h, b_h, Wc2, bc2, Wm2, bm2);
        pair_kernel<<<dim3(13,13,8), 256>>>(Wc1, bc1, Wm1, bm1, out_dy, t);
        hop_kernel<0><<<dim3(25,8), 256>>>();
        conv_kernel<FRU,0><<<dim3(25,8), 256>>>(W_ru, b_ru);
        hop_kernel<1><<<dim3(25,8), 256>>>();
        conv_kernel<FCAND,1><<<dim3(25,8), 256>>>(W_cand, b_cand);
    }

    pred_kernel<<<1600, 64>>>(Wp1, bp1, Wp2, bp2, out_pred);
}